// round 2
// baseline (speedup 1.0000x reference)
#include <cuda_runtime.h>
#include <cstdint>

// predicts: [N, C] float32 (d_in[0]), labels: [N] int (32- or 64-bit, detected) (d_in[1])
// out: scalar float32 = -(1/N) * sum_i log(predicts[i, labels[i]])

constexpr int NBLOCKS  = 1024;
constexpr int NTHREADS = 256;
constexpr int ILP      = 4;

__device__ float g_partial[NBLOCKS];

__device__ __forceinline__ bool labels_are_64bit(const int* l32) {
    // int64 labels < 2^31 have zero high words at odd int32 positions.
    // int32 labels in [0,256): 8 consecutive odd words all zero is ~5e-20.
    int acc = 0;
    #pragma unroll
    for (int j = 0; j < 8; j++)
        acc |= __ldg(l32 + 2 * j + 1);
    return acc == 0;
}

__global__ __launch_bounds__(NTHREADS)
void ce_partial_kernel(const float* __restrict__ pred,
                       const int* __restrict__ l32,
                       int n, int c) {
    const int tid  = blockIdx.x * blockDim.x + threadIdx.x;
    const int nthr = gridDim.x * blockDim.x;

    const int lstride = labels_are_64bit(l32) ? 2 : 1;  // uniform across all threads

    float s = 0.0f;

    for (int base = tid * ILP; base < n; base += nthr * ILP) {
        float p[ILP];
        #pragma unroll
        for (int j = 0; j < ILP; j++) {
            int row = base + j;
            if (row < n) {
                int idx = __ldg(l32 + (size_t)row * lstride);
                p[j] = __ldg(pred + (size_t)row * c + idx);
            } else {
                p[j] = 1.0f;  // log(1) = 0
            }
        }
        #pragma unroll
        for (int j = 0; j < ILP; j++)
            s += __logf(p[j]);
    }

    // deterministic block reduction: warp shuffle + shared tree
    #pragma unroll
    for (int o = 16; o > 0; o >>= 1)
        s += __shfl_down_sync(0xFFFFFFFFu, s, o);

    __shared__ float warp_sum[NTHREADS / 32];
    if ((threadIdx.x & 31) == 0)
        warp_sum[threadIdx.x >> 5] = s;
    __syncthreads();

    if (threadIdx.x < 32) {
        float w = (threadIdx.x < (NTHREADS / 32)) ? warp_sum[threadIdx.x] : 0.0f;
        #pragma unroll
        for (int o = 4; o > 0; o >>= 1)
            w += __shfl_down_sync(0xFFFFFFFFu, w, o);
        if (threadIdx.x == 0)
            g_partial[blockIdx.x] = w;
    }
}

__global__ __launch_bounds__(NTHREADS)
void ce_final_kernel(float* __restrict__ out, int n) {
    const int t = threadIdx.x;
    // 1024 partials, 256 threads -> 4 each
    float s = g_partial[t]
            + g_partial[t + 256]
            + g_partial[t + 512]
            + g_partial[t + 768];

    #pragma unroll
    for (int o = 16; o > 0; o >>= 1)
        s += __shfl_down_sync(0xFFFFFFFFu, s, o);

    __shared__ float warp_sum[NTHREADS / 32];
    if ((t & 31) == 0)
        warp_sum[t >> 5] = s;
    __syncthreads();

    if (t < 32) {
        float w = (t < (NTHREADS / 32)) ? warp_sum[t] : 0.0f;
        #pragma unroll
        for (int o = 4; o > 0; o >>= 1)
            w += __shfl_down_sync(0xFFFFFFFFu, w, o);
        if (t == 0)
            out[0] = -w / (float)n;
    }
}

extern "C" void kernel_launch(void* const* d_in, const int* in_sizes, int n_in,
                              void* d_out, int out_size) {
    const float* pred = (const float*)d_in[0];
    const int*   l32  = (const int*)d_in[1];
    float*       out  = (float*)d_out;

    const int n = in_sizes[1];            // number of rows (labels)
    const int c = in_sizes[0] / n;        // classes per row

    ce_partial_kernel<<<NBLOCKS, NTHREADS>>>(pred, l32, n, c);
    ce_final_kernel<<<1, NTHREADS>>>(out, n);
}

// round 3
// speedup vs baseline: 1.0761x; 1.0761x over previous
#include <cuda_runtime.h>
#include <cstdint>

// predicts: [N, C] float32 (d_in[0]); labels: [N] int32 or int64 (auto-detected) (d_in[1])
// out[0] = -(1/N) * sum_i log(predicts[i, labels[i]])

constexpr int NBLOCKS  = 1024;
constexpr int NTHREADS = 256;

__device__ float    g_partial[NBLOCKS];
__device__ unsigned g_count = 0;

__global__ __launch_bounds__(NTHREADS)
void ce_fused_kernel(const float* __restrict__ pred,
                     const int* __restrict__ l32,
                     float* __restrict__ out,
                     int n, int c) {
    __shared__ int   s_w64;
    __shared__ float warp_sum[NTHREADS / 32];

    // --- dtype detection: ONCE per block ---
    if (threadIdx.x == 0) {
        // int64 labels (<2^31) have zero high words at odd int32 slots.
        // int32 labels in [0,C): 8 consecutive odd words all zero ~ (1/C)^8.
        int acc = 0;
        #pragma unroll
        for (int j = 0; j < 8; j++)
            acc |= __ldg(l32 + 2 * j + 1);
        s_w64 = (acc == 0);
    }
    __syncthreads();
    const bool w64 = (s_w64 != 0);

    const int tid  = blockIdx.x * blockDim.x + threadIdx.x;
    const int nthr = gridDim.x * blockDim.x;
    const int nvec = n >> 2;

    float s = 0.0f;

    if (w64) {
        // int64 labels: 2x 16B vector loads per 4 rows
        const longlong2* lp = reinterpret_cast<const longlong2*>(l32);
        for (int v = tid; v < nvec; v += nthr) {
            longlong2 l01 = __ldg(lp + 2 * (size_t)v);
            longlong2 l23 = __ldg(lp + 2 * (size_t)v + 1);
            size_t r = (size_t)v * 4;
            float p0 = __ldg(pred + r       * c + (int)l01.x);
            float p1 = __ldg(pred + (r + 1) * c + (int)l01.y);
            float p2 = __ldg(pred + (r + 2) * c + (int)l23.x);
            float p3 = __ldg(pred + (r + 3) * c + (int)l23.y);
            s += __logf(p0) + __logf(p1) + __logf(p2) + __logf(p3);
        }
    } else {
        // int32 labels: 1x 16B vector load per 4 rows
        const int4* lp = reinterpret_cast<const int4*>(l32);
        for (int v = tid; v < nvec; v += nthr) {
            int4 lv = __ldg(lp + v);
            size_t r = (size_t)v * 4;
            float p0 = __ldg(pred + r       * c + lv.x);
            float p1 = __ldg(pred + (r + 1) * c + lv.y);
            float p2 = __ldg(pred + (r + 2) * c + lv.z);
            float p3 = __ldg(pred + (r + 3) * c + lv.w);
            s += __logf(p0) + __logf(p1) + __logf(p2) + __logf(p3);
        }
    }

    // tail rows (n not divisible by 4): block 0 thread 0
    if (tid == 0) {
        const int lstride = w64 ? 2 : 1;
        for (int i = nvec * 4; i < n; i++) {
            int idx = __ldg(l32 + (size_t)i * lstride);
            s += __logf(__ldg(pred + (size_t)i * c + idx));
        }
    }

    // --- deterministic block reduction ---
    #pragma unroll
    for (int o = 16; o > 0; o >>= 1)
        s += __shfl_down_sync(0xFFFFFFFFu, s, o);
    if ((threadIdx.x & 31) == 0)
        warp_sum[threadIdx.x >> 5] = s;
    __syncthreads();

    __shared__ bool s_last;
    if (threadIdx.x == 0) {
        float b = 0.0f;
        #pragma unroll
        for (int w = 0; w < NTHREADS / 32; w++)
            b += warp_sum[w];
        g_partial[blockIdx.x] = b;
        __threadfence();
        unsigned prev = atomicAdd(&g_count, 1u);
        s_last = (prev == (unsigned)(gridDim.x - 1));
    }
    __syncthreads();

    // --- last block: fixed-order final reduction (deterministic) ---
    if (s_last) {
        const int t = threadIdx.x;
        volatile float* gp = g_partial;
        float f = gp[t] + gp[t + 256] + gp[t + 512] + gp[t + 768];

        #pragma unroll
        for (int o = 16; o > 0; o >>= 1)
            f += __shfl_down_sync(0xFFFFFFFFu, f, o);
        if ((t & 31) == 0)
            warp_sum[t >> 5] = f;
        __syncthreads();

        if (t == 0) {
            float tot = 0.0f;
            #pragma unroll
            for (int w = 0; w < NTHREADS / 32; w++)
                tot += warp_sum[w];
            out[0] = -tot / (float)n;
            g_count = 0;   // reset for next graph replay
        }
    }
}

extern "C" void kernel_launch(void* const* d_in, const int* in_sizes, int n_in,
                              void* d_out, int out_size) {
    const float* pred = (const float*)d_in[0];
    const int*   l32  = (const int*)d_in[1];
    float*       out  = (float*)d_out;

    const int n = in_sizes[1];
    const int c = in_sizes[0] / n;

    ce_fused_kernel<<<NBLOCKS, NTHREADS>>>(pred, l32, out, n, c);
}